// round 8
// baseline (speedup 1.0000x reference)
#include <cuda_runtime.h>
#include <math.h>

#define L_ 2048
#define H_ 2048
#define I_ 4096
#define N_ 16
#define K_ 4
#define R_ 128
#define SPN_ (R_ + 2 * N_)   // 160
#define SPLITK_ 4

static __device__ __constant__ float kEPS = 1e-6f;

// ---------------- scratch (device globals; no allocation allowed) ----------
__device__ float g_proj[(size_t)L_ * 2 * I_];          // [L, 2I] in_proj output
__device__ float g_xc[(size_t)L_ * I_];                // [L, I]  conv+silu output
__device__ float g_sp[(size_t)SPLITK_ * L_ * SPN_];    // 4 x [L, 160] split-K partials
__device__ float g_dtr[(size_t)L_ * R_];               // [L, 128] rmsnorm'd dt rank
__device__ float g_bc[(size_t)L_ * 32];                // [L, 16x(B,C) interleaved]
__device__ float g_dt[(size_t)L_ * I_];                // [L, I]  softplus dt
__device__ float g_y[(size_t)L_ * I_];                 // [L, I]  gated scan output

// ============================================================================
// Split-TF32 tensor-core GEMM: C[M,N] = A[M,K-chunk] * B[N,K-chunk]^T (+ epi)
//   - blockIdx.x -> M tile, blockIdx.y -> N tile (col-major wave: A L2-resident)
//   - blockIdx.z -> split-K slice: k-offset z*K, output C + z*M*N (partials)
//   - lda = row stride of A and B (= full K); K = chunk depth, % 32 == 0.
//   - M % 128 == 0; N arbitrary (B rows zero-filled, stores guarded).
//   - hi/lo tf32 split (3 MMAs) -> ~fp32 accuracy.
//   - 2-stage cp.async.cg pipeline, dynamic smem (72 KB).
// EPI: 0 = plain store, 1 = softplus(acc + bias[col]).
// ============================================================================
#define TGK 32
#define TGLDS 36                           // 32 + 4 pad: conflict-free frag loads
#define TG_SMEM_FLOATS (4 * 128 * TGLDS)   // 2 bufs x (As + Bs)
#define TG_SMEM_BYTES  (TG_SMEM_FLOATS * 4)

__device__ __forceinline__ void split_tf32(float x, unsigned& hi, unsigned& lo) {
    unsigned h;
    asm("cvt.rna.tf32.f32 %0, %1;" : "=r"(h) : "f"(x));
    float r = x - __uint_as_float(h);
    unsigned l;
    asm("cvt.rna.tf32.f32 %0, %1;" : "=r"(l) : "f"(r));
    hi = h; lo = l;
}

__device__ __forceinline__ void mma_tf32(float* c, const unsigned* a, const unsigned* b) {
    asm volatile(
        "mma.sync.aligned.m16n8k8.row.col.f32.tf32.tf32.f32 "
        "{%0,%1,%2,%3}, {%4,%5,%6,%7}, {%8,%9}, {%0,%1,%2,%3};"
        : "+f"(c[0]), "+f"(c[1]), "+f"(c[2]), "+f"(c[3])
        : "r"(a[0]), "r"(a[1]), "r"(a[2]), "r"(a[3]), "r"(b[0]), "r"(b[1]));
}

__device__ __forceinline__ void cp_async16(float* smem, const float* gmem, int src_bytes) {
    unsigned saddr = (unsigned)__cvta_generic_to_shared(smem);
    asm volatile("cp.async.cg.shared.global [%0], [%1], 16, %2;\n"
                 :: "r"(saddr), "l"(gmem), "r"(src_bytes));
}

template <int EPI>
__global__ __launch_bounds__(256) void tf32_gemm_abT(
    const float* __restrict__ A, const float* __restrict__ B,
    float* __restrict__ C, int M, int N, int K, int lda,
    const float* __restrict__ bias)
{
    extern __shared__ __align__(16) float smem[];
    float* As = smem;                       // [2][128*TGLDS]
    float* Bs = smem + 2 * 128 * TGLDS;     // [2][128*TGLDS]

    // split-K slice
    const int koff = blockIdx.z * K;
    A += koff;
    B += koff;
    C += (size_t)blockIdx.z * M * N;

    const int tid  = threadIdx.x;
    const int brow = blockIdx.x * 128;      // M tile (x-fastest -> col-major sweep)
    const int bcol = blockIdx.y * 128;      // N tile
    const int lane = tid & 31;
    const int w    = tid >> 5;
    const int wm   = (w & 1) << 6;   // 0 / 64
    const int wn   = (w >> 1) << 5;  // 0 / 32 / 64 / 96
    const int qid  = lane >> 2;      // 0..7
    const int qt   = lane & 3;       // 0..3

    const int lr = tid >> 3;         // 0..31
    const int lc = (tid & 7) * 4;    // 0,4,...,28

    float acc[4][4][4];
#pragma unroll
    for (int im = 0; im < 4; im++)
#pragma unroll
        for (int in = 0; in < 4; in++)
#pragma unroll
            for (int q = 0; q < 4; q++) acc[im][in][q] = 0.f;

    const int nslab = K / TGK;

    // ---- async-load one 128x32 A slab + 128x32 B slab into buffer `buf` ----
    auto issue = [&](int k0, int buf) {
        float* as = As + buf * 128 * TGLDS;
        float* bs = Bs + buf * 128 * TGLDS;
#pragma unroll
        for (int p = 0; p < 4; p++) {
            int r = lr + 32 * p;
            cp_async16(&as[r * TGLDS + lc],
                       A + (size_t)(brow + r) * lda + k0 + lc, 16);
            int browB = bcol + r;
            bool bv = browB < N;
            cp_async16(&bs[r * TGLDS + lc],
                       B + (size_t)(bv ? browB : 0) * lda + k0 + lc, bv ? 16 : 0);
        }
        asm volatile("cp.async.commit_group;\n");
    };

    issue(0, 0);

    for (int s = 0; s < nslab; s++) {
        const int buf = s & 1;
        if (s + 1 < nslab) {
            issue((s + 1) * TGK, buf ^ 1);
            asm volatile("cp.async.wait_group 1;\n");
        } else {
            asm volatile("cp.async.wait_group 0;\n");
        }
        __syncthreads();

        const float* as = As + buf * 128 * TGLDS;
        const float* bs = Bs + buf * 128 * TGLDS;
#pragma unroll
        for (int kk = 0; kk < 4; kk++) {
            const int kb = kk * 8;
            unsigned ah[4][4], al[4][4];
#pragma unroll
            for (int im = 0; im < 4; im++) {
                const float* ap = &as[(wm + im * 16 + qid) * TGLDS + kb + qt];
                split_tf32(ap[0],             ah[im][0], al[im][0]);
                split_tf32(ap[8 * TGLDS],     ah[im][1], al[im][1]);
                split_tf32(ap[4],             ah[im][2], al[im][2]);
                split_tf32(ap[8 * TGLDS + 4], ah[im][3], al[im][3]);
            }
            unsigned bh[4][2], bl[4][2];
#pragma unroll
            for (int in = 0; in < 4; in++) {
                const float* bp = &bs[(wn + in * 8 + qid) * TGLDS + kb + qt];
                split_tf32(bp[0], bh[in][0], bl[in][0]);
                split_tf32(bp[4], bh[in][1], bl[in][1]);
            }
#pragma unroll
            for (int im = 0; im < 4; im++)
#pragma unroll
                for (int in = 0; in < 4; in++) {
                    mma_tf32(acc[im][in], ah[im], bh[in]);  // hi*hi
                    mma_tf32(acc[im][in], ah[im], bl[in]);  // hi*lo
                    mma_tf32(acc[im][in], al[im], bh[in]);  // lo*hi
                }
        }
        __syncthreads();
    }

#pragma unroll
    for (int im = 0; im < 4; im++) {
        int r0 = brow + wm + im * 16 + qid;
#pragma unroll
        for (int in = 0; in < 4; in++) {
            int col = bcol + wn + in * 8 + 2 * qt;
            if (col < N) {
                float v[4] = {acc[im][in][0], acc[im][in][1],
                              acc[im][in][2], acc[im][in][3]};
                if (EPI == 1) {
                    float b0 = bias[col], b1 = bias[col + 1];
                    v[0] += b0; v[1] += b1; v[2] += b0; v[3] += b1;
#pragma unroll
                    for (int q = 0; q < 4; q++)
                        v[q] = (v[q] > 20.f) ? v[q] : log1pf(__expf(v[q]));
                }
                *reinterpret_cast<float2*>(&C[(size_t)r0 * N + col]) =
                    make_float2(v[0], v[1]);
                *reinterpret_cast<float2*>(&C[(size_t)(r0 + 8) * N + col]) =
                    make_float2(v[2], v[3]);
            }
        }
    }
}

// ---------------- depthwise causal conv1d (K=4) + SiLU ---------------------
__global__ __launch_bounds__(256) void conv_silu_kernel(
    const float* __restrict__ proj, const float* __restrict__ cw,
    const float* __restrict__ cb, float* __restrict__ xc)
{
    int idx = blockIdx.x * blockDim.x + threadIdx.x;   // over L*I
    int t = idx >> 12;          // / I_
    int i = idx & (I_ - 1);
    float4 w = reinterpret_cast<const float4*>(cw)[i]; // conv_w[i, 0..3]
    float acc = cb[i];
    const float* col = proj + i;
    if (t >= 3) {
        acc += w.x * col[(size_t)(t - 3) * (2 * I_)];
        acc += w.y * col[(size_t)(t - 2) * (2 * I_)];
        acc += w.z * col[(size_t)(t - 1) * (2 * I_)];
        acc += w.w * col[(size_t)t * (2 * I_)];
    } else {
        const float* wv = reinterpret_cast<const float*>(&w);
#pragma unroll
        for (int k = 0; k < K_; k++) {
            int tt = t - (K_ - 1) + k;
            if (tt >= 0) acc += wv[k] * col[(size_t)tt * (2 * I_)];
        }
    }
    xc[idx] = acc / (1.f + __expf(-acc));  // silu
}

// ---------------- fused split-K reduce + 3-way RMSNorm ---------------------
// sp holds 4 partials of [L,160]; sum then rmsnorm.
// bc output layout: [t][n] -> (B, C) interleaved pairs: bc[t*32 + 2n] = B_n,
// bc[t*32 + 2n + 1] = C_n  (scan loads both with one float2).
__global__ __launch_bounds__(128) void rmsnorm_kernel(
    const float* __restrict__ sp, const float* __restrict__ wdt,
    const float* __restrict__ wb, const float* __restrict__ wc,
    float* __restrict__ dtr, float* __restrict__ bc)
{
    const size_t PS = (size_t)L_ * SPN_;   // partial stride
    int warp = threadIdx.x >> 5, lane = threadIdx.x & 31;
    int t = blockIdx.x * 4 + warp;
    const float* row = sp + (size_t)t * SPN_;

    float v0 = 0.f, v1 = 0.f, v2 = 0.f, v3 = 0.f, v = 0.f;
#pragma unroll
    for (int p = 0; p < SPLITK_; p++) {
        const float* rp = row + p * PS;
        v0 += rp[lane];       v1 += rp[lane + 32];
        v2 += rp[lane + 64];  v3 += rp[lane + 96];
        v  += rp[R_ + lane];  // lanes 0..15: B_n, lanes 16..31: C_(lane-16)
    }

    float ss = v0 * v0 + v1 * v1 + v2 * v2 + v3 * v3;
#pragma unroll
    for (int o = 16; o; o >>= 1) ss += __shfl_xor_sync(0xffffffffu, ss, o);
    float rinv = rsqrtf(ss * (1.f / R_) + kEPS);
    float* drow = dtr + (size_t)t * R_;
    drow[lane]      = v0 * rinv * wdt[lane];
    drow[lane + 32] = v1 * rinv * wdt[lane + 32];
    drow[lane + 64] = v2 * rinv * wdt[lane + 64];
    drow[lane + 96] = v3 * rinv * wdt[lane + 96];

    float sv = v * v;
#pragma unroll
    for (int o = 8; o; o >>= 1) sv += __shfl_xor_sync(0xffffffffu, sv, o);
    float w = (lane < 16) ? wb[lane] : wc[lane - 16];
    float r = rsqrtf(sv * (1.f / N_) + kEPS);
    int slot = (lane < 16) ? (2 * lane) : (2 * (lane - 16) + 1);
    bc[(size_t)t * 32 + slot] = v * r * w;
}

// ---------------- selective scan + gated output (unrolled x4) --------------
__global__ __launch_bounds__(128) void scan_kernel(
    const float* __restrict__ xc, const float* __restrict__ dt,
    const float* __restrict__ bc, const float* __restrict__ Aw,
    const float* __restrict__ Dw, const float* __restrict__ proj,
    float* __restrict__ y)
{
    int tid = threadIdx.x;
    int c = tid >> 4, n = tid & 15;
    int i = blockIdx.x * 8 + c;
    float a = Aw[(size_t)i * N_ + n];
    float d = Dw[i];
    float state = 0.f;

    const float* dtp = dt + i;
    const float* xcp = xc + i;
    const float* gp  = proj + I_ + i;
    const float2* bcp = reinterpret_cast<const float2*>(bc) + n;  // (B,C) pairs

    for (int t = 0; t < L_; t += 4) {
        float dtv[4], xv[4];
        float2 bcv[4];
#pragma unroll
        for (int u = 0; u < 4; u++) {
            dtv[u] = dtp[(size_t)(t + u) * I_];
            xv[u]  = xcp[(size_t)(t + u) * I_];
            bcv[u] = bcp[(t + u) * 16];       // {B_n, C_n} at token t+u
        }

        float s[4];
#pragma unroll
        for (int u = 0; u < 4; u++) {
            state = state * __expf(dtv[u] * a) + dtv[u] * xv[u] * bcv[u].x;
            float su = state * bcv[u].y;
            su += __shfl_xor_sync(0xffffffffu, su, 8);
            su += __shfl_xor_sync(0xffffffffu, su, 4);
            su += __shfl_xor_sync(0xffffffffu, su, 2);
            su += __shfl_xor_sync(0xffffffffu, su, 1);
            s[u] = su;
        }

        if (n == 0) {
#pragma unroll
            for (int u = 0; u < 4; u++) {
                float g = gp[(size_t)(t + u) * (2 * I_)];
                float sg = g / (1.f + __expf(-g));
                y[(size_t)(t + u) * I_ + i] = (s[u] + xv[u] * d) * sg;
            }
        }
    }
}

// ---------------------------------------------------------------------------
extern "C" void kernel_launch(void* const* d_in, const int* in_sizes, int n_in,
                              void* d_out, int out_size)
{
    const float* hs        = (const float*)d_in[0];   // [L, H]
    const float* in_proj_w = (const float*)d_in[1];   // [2I, H]
    const float* conv_w    = (const float*)d_in[2];   // [I, 4]
    const float* conv_b    = (const float*)d_in[3];   // [I]
    const float* x_proj_w  = (const float*)d_in[4];   // [R+2N, I]
    const float* dt_ln_w   = (const float*)d_in[5];   // [R]
    const float* b_ln_w    = (const float*)d_in[6];   // [N]
    const float* c_ln_w    = (const float*)d_in[7];   // [N]
    const float* dt_proj_w = (const float*)d_in[8];   // [I, R]
    const float* dt_proj_b = (const float*)d_in[9];   // [I]
    const float* A         = (const float*)d_in[10];  // [I, N]
    const float* D         = (const float*)d_in[11];  // [I]
    const float* out_proj_w= (const float*)d_in[12];  // [H, I]
    float* out             = (float*)d_out;           // [L, H]

    float *proj, *xc, *sp, *dtr, *bcv, *dtv, *yv;
    cudaGetSymbolAddress((void**)&proj, g_proj);
    cudaGetSymbolAddress((void**)&xc,   g_xc);
    cudaGetSymbolAddress((void**)&sp,   g_sp);
    cudaGetSymbolAddress((void**)&dtr,  g_dtr);
    cudaGetSymbolAddress((void**)&bcv,  g_bc);
    cudaGetSymbolAddress((void**)&dtv,  g_dt);
    cudaGetSymbolAddress((void**)&yv,   g_y);

    // opt-in to >48KB dynamic smem (host attribute set; idempotent, capture-safe)
    cudaFuncSetAttribute(tf32_gemm_abT<0>,
                         cudaFuncAttributeMaxDynamicSharedMemorySize, TG_SMEM_BYTES);
    cudaFuncSetAttribute(tf32_gemm_abT<1>,
                         cudaFuncAttributeMaxDynamicSharedMemorySize, TG_SMEM_BYTES);

    // grid: x = M tiles (col-major wave -> A stays L2-resident), y = N tiles
    // 1) proj[L, 2I] = hs @ in_proj_w^T
    tf32_gemm_abT<0><<<dim3(L_ / 128, 2 * I_ / 128), 256, TG_SMEM_BYTES>>>(
        hs, in_proj_w, proj, L_, 2 * I_, H_, H_, nullptr);

    // 2) xc = silu(causal depthwise conv(proj[:, :I]))
    conv_silu_kernel<<<(L_ * I_) / 256, 256>>>(proj, conv_w, conv_b, xc);

    // 3) sp partials = xc @ x_proj_w^T, split-K x4 (z-slices), 128 CTAs
    tf32_gemm_abT<0><<<dim3(L_ / 128, 2, SPLITK_), 256, TG_SMEM_BYTES>>>(
        xc, x_proj_w, sp, L_, SPN_, I_ / SPLITK_, I_, nullptr);

    // 4) split-K reduce + per-branch rmsnorm -> dtr[L,128], bc[L,16x(B,C)]
    rmsnorm_kernel<<<L_ / 4, 128>>>(sp, dt_ln_w, b_ln_w, c_ln_w, dtr, bcv);

    // 5) dt[L, I] = softplus(dtr @ dt_proj_w^T + dt_proj_b)
    tf32_gemm_abT<1><<<dim3(L_ / 128, I_ / 128), 256, TG_SMEM_BYTES>>>(
        dtr, dt_proj_w, dtv, L_, I_, R_, R_, dt_proj_b);

    // 6) selective scan + (ys + xc*D) * silu(gate) -> y[L, I]
    scan_kernel<<<I_ / 8, 128>>>(xc, dtv, bcv, A, D, proj, yv);

    // 7) out[L, H] = y @ out_proj_w^T
    tf32_gemm_abT<0><<<dim3(L_ / 128, H_ / 128), 256, TG_SMEM_BYTES>>>(
        yv, out_proj_w, out, L_, H_, I_, I_, nullptr);
}

// round 9
// speedup vs baseline: 1.2033x; 1.2033x over previous
#include <cuda_runtime.h>
#include <cuda_bf16.h>
#include <math.h>

#define L_ 2048
#define H_ 2048
#define I_ 4096
#define N_ 16
#define K_ 4
#define R_ 128
#define SPN_ (R_ + 2 * N_)   // 160
#define SPLITK_ 4

static __device__ __constant__ float kEPS = 1e-6f;

// ---------------- scratch (device globals; no allocation allowed) ----------
__device__ float g_proj[(size_t)L_ * 2 * I_];          // [L, 2I] in_proj output
__device__ float g_xc[(size_t)L_ * I_];                // [L, I]  conv+silu (fp32, scan)
__device__ float g_sp[(size_t)SPLITK_ * L_ * SPN_];    // 4 x [L, 160] split-K partials
__device__ float g_bc[(size_t)L_ * 32];                // [L, 16x(B,C) interleaved]
__device__ float g_dt[(size_t)L_ * I_];                // [L, I]  softplus dt

// bf16 hi/lo plane pairs: [0..n) = hi plane, [n..2n) = lo plane
__device__ __nv_bfloat16 g_hs_p[(size_t)2 * L_ * H_];
__device__ __nv_bfloat16 g_ipw_p[(size_t)2 * 2 * I_ * H_];
__device__ __nv_bfloat16 g_xc_p[(size_t)2 * L_ * I_];
__device__ __nv_bfloat16 g_xpw_p[(size_t)2 * SPN_ * I_];
__device__ __nv_bfloat16 g_dtr_p[(size_t)2 * L_ * R_];
__device__ __nv_bfloat16 g_dtpw_p[(size_t)2 * I_ * R_];
__device__ __nv_bfloat16 g_y_p[(size_t)2 * L_ * I_];
__device__ __nv_bfloat16 g_opw_p[(size_t)2 * H_ * I_];

__device__ __forceinline__ void split_bf16(float f, __nv_bfloat16& h, __nv_bfloat16& l) {
    h = __float2bfloat16_rn(f);
    l = __float2bfloat16_rn(f - __bfloat162float(h));
}

// ---------------- fp32 -> bf16 hi/lo plane split (elementwise) -------------
__global__ __launch_bounds__(256) void split_kernel(
    const float* __restrict__ src, __nv_bfloat16* __restrict__ planes, size_t n)
{
    size_t idx = (size_t)blockIdx.x * blockDim.x + threadIdx.x;
    if (idx < n) {
        __nv_bfloat16 h, l;
        split_bf16(src[idx], h, l);
        planes[idx]     = h;
        planes[n + idx] = l;
    }
}

// ============================================================================
// Split-BF16 tensor-core GEMM: C[M,N] = A[M,Kc] * B[N,Kc]^T (+ epilogue)
//   A,B given as pre-split bf16 hi/lo planes (k-contiguous, row stride lda).
//   hi/lo 3-MMA (hh + hl + lh) m16n8k16 -> ~17-bit effective mantissa.
//   - blockIdx.x -> M tile, blockIdx.y -> N tile, blockIdx.z -> split-K slice
//   - M % 128 == 0, Kc % 32 == 0; N arbitrary (zfill + guarded stores).
//   - 2-stage cp.async.cg pipeline; smem 80KB (4 planes x 128x40-half rows).
// EPI: 0 = plain store, 1 = softplus(acc + bias[col]).
// ============================================================================
#define TGK 32
#define PLH (128 * 40)                    // halves per plane-slab (40-half pitch)
#define TG_SMEM_BYTES (2 * 4 * PLH * 2)   // 2 bufs x 4 planes x PLH halves x 2B

__device__ __forceinline__ void mma_bf16(float* c, const unsigned* a, const unsigned* b) {
    asm volatile(
        "mma.sync.aligned.m16n8k16.row.col.f32.bf16.bf16.f32 "
        "{%0,%1,%2,%3}, {%4,%5,%6,%7}, {%8,%9}, {%0,%1,%2,%3};"
        : "+f"(c[0]), "+f"(c[1]), "+f"(c[2]), "+f"(c[3])
        : "r"(a[0]), "r"(a[1]), "r"(a[2]), "r"(a[3]), "r"(b[0]), "r"(b[1]));
}

__device__ __forceinline__ void cp_async16(void* smem, const void* gmem, int src_bytes) {
    unsigned saddr = (unsigned)__cvta_generic_to_shared(smem);
    asm volatile("cp.async.cg.shared.global [%0], [%1], 16, %2;\n"
                 :: "r"(saddr), "l"(gmem), "r"(src_bytes));
}

template <int EPI>
__global__ __launch_bounds__(256) void bf16_gemm_abT(
    const __nv_bfloat16* __restrict__ Ah, const __nv_bfloat16* __restrict__ Al,
    const __nv_bfloat16* __restrict__ Bh, const __nv_bfloat16* __restrict__ Bl,
    float* __restrict__ C, int M, int N, int K, int lda,
    const float* __restrict__ bias)
{
    extern __shared__ __align__(16) __nv_bfloat16 smem[];

    // split-K slice
    const int koff = blockIdx.z * K;
    Ah += koff; Al += koff; Bh += koff; Bl += koff;
    C += (size_t)blockIdx.z * M * N;

    const int tid  = threadIdx.x;
    const int brow = blockIdx.x * 128;      // M tile (x-fastest -> col-major sweep)
    const int bcol = blockIdx.y * 128;      // N tile
    const int lane = tid & 31;
    const int w    = tid >> 5;
    const int wm   = (w & 1) << 6;   // 0 / 64
    const int wn   = (w >> 1) << 5;  // 0 / 32 / 64 / 96
    const int qid  = lane >> 2;      // 0..7
    const int qt   = lane & 3;       // 0..3

    float acc[4][4][4];
#pragma unroll
    for (int im = 0; im < 4; im++)
#pragma unroll
        for (int in = 0; in < 4; in++)
#pragma unroll
            for (int q = 0; q < 4; q++) acc[im][in][q] = 0.f;

    const int nslab = K / TGK;

    // ---- async-load 128x32-half slabs of 4 planes into buffer `buf` -------
    auto issue = [&](int k0, int buf) {
        __nv_bfloat16* s = smem + buf * 4 * PLH;
#pragma unroll
        for (int j = 0; j < 2; j++) {
            int chunk = tid * 2 + j;          // 0..511 (16B chunks per plane)
            int row = chunk >> 2;             // 0..127
            int co  = (chunk & 3) * 8;        // half offset in row: 0,8,16,24
            int so  = row * 40 + co;
            size_t aoff = (size_t)(brow + row) * lda + k0 + co;
            cp_async16(&s[so],           Ah + aoff, 16);
            cp_async16(&s[PLH + so],     Al + aoff, 16);
            int browB = bcol + row;
            bool bv = browB < N;
            size_t boff = (size_t)(bv ? browB : 0) * lda + k0 + co;
            cp_async16(&s[2 * PLH + so], Bh + boff, bv ? 16 : 0);
            cp_async16(&s[3 * PLH + so], Bl + boff, bv ? 16 : 0);
        }
        asm volatile("cp.async.commit_group;\n");
    };

    issue(0, 0);

    for (int s = 0; s < nslab; s++) {
        const int buf = s & 1;
        if (s + 1 < nslab) {
            issue((s + 1) * TGK, buf ^ 1);
            asm volatile("cp.async.wait_group 1;\n");
        } else {
            asm volatile("cp.async.wait_group 0;\n");
        }
        __syncthreads();

        const __nv_bfloat16* sb = smem + buf * 4 * PLH;
#pragma unroll
        for (int kk = 0; kk < 2; kk++) {
            const int c0 = kk * 16 + 2 * qt;
            const int c1 = c0 + 8;
            unsigned aH[4][4], aL[4][4];
#pragma unroll
            for (int im = 0; im < 4; im++) {
                int r0 = (wm + im * 16 + qid) * 40;
                int r8 = r0 + 8 * 40;
                aH[im][0] = *(const unsigned*)&sb[r0 + c0];
                aH[im][1] = *(const unsigned*)&sb[r8 + c0];
                aH[im][2] = *(const unsigned*)&sb[r0 + c1];
                aH[im][3] = *(const unsigned*)&sb[r8 + c1];
                aL[im][0] = *(const unsigned*)&sb[PLH + r0 + c0];
                aL[im][1] = *(const unsigned*)&sb[PLH + r8 + c0];
                aL[im][2] = *(const unsigned*)&sb[PLH + r0 + c1];
                aL[im][3] = *(const unsigned*)&sb[PLH + r8 + c1];
            }
            unsigned bH[4][2], bL[4][2];
#pragma unroll
            for (int in = 0; in < 4; in++) {
                int rn = (wn + in * 8 + qid) * 40;
                bH[in][0] = *(const unsigned*)&sb[2 * PLH + rn + c0];
                bH[in][1] = *(const unsigned*)&sb[2 * PLH + rn + c1];
                bL[in][0] = *(const unsigned*)&sb[3 * PLH + rn + c0];
                bL[in][1] = *(const unsigned*)&sb[3 * PLH + rn + c1];
            }
#pragma unroll
            for (int im = 0; im < 4; im++)
#pragma unroll
                for (int in = 0; in < 4; in++) {
                    mma_bf16(acc[im][in], aH[im], bH[in]);  // hi*hi
                    mma_bf16(acc[im][in], aH[im], bL[in]);  // hi*lo
                    mma_bf16(acc[im][in], aL[im], bH[in]);  // lo*hi
                }
        }
        __syncthreads();
    }

#pragma unroll
    for (int im = 0; im < 4; im++) {
        int r0 = brow + wm + im * 16 + qid;
#pragma unroll
        for (int in = 0; in < 4; in++) {
            int col = bcol + wn + in * 8 + 2 * qt;
            if (col < N) {
                float v[4] = {acc[im][in][0], acc[im][in][1],
                              acc[im][in][2], acc[im][in][3]};
                if (EPI == 1) {
                    float b0 = bias[col], b1 = bias[col + 1];
                    v[0] += b0; v[1] += b1; v[2] += b0; v[3] += b1;
#pragma unroll
                    for (int q = 0; q < 4; q++)
                        v[q] = (v[q] > 20.f) ? v[q] : log1pf(__expf(v[q]));
                }
                *reinterpret_cast<float2*>(&C[(size_t)r0 * N + col]) =
                    make_float2(v[0], v[1]);
                *reinterpret_cast<float2*>(&C[(size_t)(r0 + 8) * N + col]) =
                    make_float2(v[2], v[3]);
            }
        }
    }
}

// ---------------- depthwise causal conv1d (K=4) + SiLU + plane split -------
__global__ __launch_bounds__(256) void conv_silu_kernel(
    const float* __restrict__ proj, const float* __restrict__ cw,
    const float* __restrict__ cb, float* __restrict__ xc,
    __nv_bfloat16* __restrict__ xcp)
{
    int idx = blockIdx.x * blockDim.x + threadIdx.x;   // over L*I
    int t = idx >> 12;          // / I_
    int i = idx & (I_ - 1);
    float4 w = reinterpret_cast<const float4*>(cw)[i]; // conv_w[i, 0..3]
    float acc = cb[i];
    const float* col = proj + i;
    if (t >= 3) {
        acc += w.x * col[(size_t)(t - 3) * (2 * I_)];
        acc += w.y * col[(size_t)(t - 2) * (2 * I_)];
        acc += w.z * col[(size_t)(t - 1) * (2 * I_)];
        acc += w.w * col[(size_t)t * (2 * I_)];
    } else {
        const float* wv = reinterpret_cast<const float*>(&w);
#pragma unroll
        for (int k = 0; k < K_; k++) {
            int tt = t - (K_ - 1) + k;
            if (tt >= 0) acc += wv[k] * col[(size_t)tt * (2 * I_)];
        }
    }
    float s = acc / (1.f + __expf(-acc));  // silu
    xc[idx] = s;
    __nv_bfloat16 h, l;
    split_bf16(s, h, l);
    xcp[idx] = h;
    xcp[(size_t)L_ * I_ + idx] = l;
}

// ---------------- fused split-K reduce + 3-way RMSNorm ---------------------
// sp holds 4 partials of [L,160]; sum then rmsnorm.
// dtr output -> bf16 hi/lo planes; bc output (B,C) interleaved pairs.
__global__ __launch_bounds__(128) void rmsnorm_kernel(
    const float* __restrict__ sp, const float* __restrict__ wdt,
    const float* __restrict__ wb, const float* __restrict__ wc,
    __nv_bfloat16* __restrict__ dtrp, float* __restrict__ bc)
{
    const size_t PS = (size_t)L_ * SPN_;   // partial stride
    const size_t DP = (size_t)L_ * R_;     // dtr plane stride
    int warp = threadIdx.x >> 5, lane = threadIdx.x & 31;
    int t = blockIdx.x * 4 + warp;
    const float* row = sp + (size_t)t * SPN_;

    float v0 = 0.f, v1 = 0.f, v2 = 0.f, v3 = 0.f, v = 0.f;
#pragma unroll
    for (int p = 0; p < SPLITK_; p++) {
        const float* rp = row + p * PS;
        v0 += rp[lane];       v1 += rp[lane + 32];
        v2 += rp[lane + 64];  v3 += rp[lane + 96];
        v  += rp[R_ + lane];  // lanes 0..15: B_n, lanes 16..31: C_(lane-16)
    }

    float ss = v0 * v0 + v1 * v1 + v2 * v2 + v3 * v3;
#pragma unroll
    for (int o = 16; o; o >>= 1) ss += __shfl_xor_sync(0xffffffffu, ss, o);
    float rinv = rsqrtf(ss * (1.f / R_) + kEPS);
    size_t base = (size_t)t * R_;
    float d0 = v0 * rinv * wdt[lane];
    float d1 = v1 * rinv * wdt[lane + 32];
    float d2 = v2 * rinv * wdt[lane + 64];
    float d3 = v3 * rinv * wdt[lane + 96];
    __nv_bfloat16 h, l;
    split_bf16(d0, h, l); dtrp[base + lane]      = h; dtrp[DP + base + lane]      = l;
    split_bf16(d1, h, l); dtrp[base + lane + 32] = h; dtrp[DP + base + lane + 32] = l;
    split_bf16(d2, h, l); dtrp[base + lane + 64] = h; dtrp[DP + base + lane + 64] = l;
    split_bf16(d3, h, l); dtrp[base + lane + 96] = h; dtrp[DP + base + lane + 96] = l;

    float sv = v * v;
#pragma unroll
    for (int o = 8; o; o >>= 1) sv += __shfl_xor_sync(0xffffffffu, sv, o);
    float wgt = (lane < 16) ? wb[lane] : wc[lane - 16];
    float r = rsqrtf(sv * (1.f / N_) + kEPS);
    int slot = (lane < 16) ? (2 * lane) : (2 * (lane - 16) + 1);
    bc[(size_t)t * 32 + slot] = v * r * wgt;
}

// ---------------- selective scan + gated output (unrolled x4) --------------
// writes y as bf16 hi/lo planes (consumed by out_proj GEMM)
__global__ __launch_bounds__(128) void scan_kernel(
    const float* __restrict__ xc, const float* __restrict__ dt,
    const float* __restrict__ bc, const float* __restrict__ Aw,
    const float* __restrict__ Dw, const float* __restrict__ proj,
    __nv_bfloat16* __restrict__ yp)
{
    const size_t YP = (size_t)L_ * I_;
    int tid = threadIdx.x;
    int c = tid >> 4, n = tid & 15;
    int i = blockIdx.x * 8 + c;
    float a = Aw[(size_t)i * N_ + n];
    float d = Dw[i];
    float state = 0.f;

    const float* dtp = dt + i;
    const float* xcp = xc + i;
    const float* gp  = proj + I_ + i;
    const float2* bcp = reinterpret_cast<const float2*>(bc) + n;  // (B,C) pairs

    for (int t = 0; t < L_; t += 4) {
        float dtv[4], xv[4];
        float2 bcv[4];
#pragma unroll
        for (int u = 0; u < 4; u++) {
            dtv[u] = dtp[(size_t)(t + u) * I_];
            xv[u]  = xcp[(size_t)(t + u) * I_];
            bcv[u] = bcp[(t + u) * 16];       // {B_n, C_n} at token t+u
        }

        float s[4];
#pragma unroll
        for (int u = 0; u < 4; u++) {
            state = state * __expf(dtv[u] * a) + dtv[u] * xv[u] * bcv[u].x;
            float su = state * bcv[u].y;
            su += __shfl_xor_sync(0xffffffffu, su, 8);
            su += __shfl_xor_sync(0xffffffffu, su, 4);
            su += __shfl_xor_sync(0xffffffffu, su, 2);
            su += __shfl_xor_sync(0xffffffffu, su, 1);
            s[u] = su;
        }

        if (n == 0) {
#pragma unroll
            for (int u = 0; u < 4; u++) {
                float g = gp[(size_t)(t + u) * (2 * I_)];
                float sg = g / (1.f + __expf(-g));
                float yv = (s[u] + xv[u] * d) * sg;
                __nv_bfloat16 h, l;
                split_bf16(yv, h, l);
                size_t o = (size_t)(t + u) * I_ + i;
                yp[o]      = h;
                yp[YP + o] = l;
            }
        }
    }
}

// ---------------------------------------------------------------------------
extern "C" void kernel_launch(void* const* d_in, const int* in_sizes, int n_in,
                              void* d_out, int out_size)
{
    const float* hs        = (const float*)d_in[0];   // [L, H]
    const float* in_proj_w = (const float*)d_in[1];   // [2I, H]
    const float* conv_w    = (const float*)d_in[2];   // [I, 4]
    const float* conv_b    = (const float*)d_in[3];   // [I]
    const float* x_proj_w  = (const float*)d_in[4];   // [R+2N, I]
    const float* dt_ln_w   = (const float*)d_in[5];   // [R]
    const float* b_ln_w    = (const float*)d_in[6];   // [N]
    const float* c_ln_w    = (const float*)d_in[7];   // [N]
    const float* dt_proj_w = (const float*)d_in[8];   // [I, R]
    const float* dt_proj_b = (const float*)d_in[9];   // [I]
    const float* A         = (const float*)d_in[10];  // [I, N]
    const float* D         = (const float*)d_in[11];  // [I]
    const float* out_proj_w= (const float*)d_in[12];  // [H, I]
    float* out             = (float*)d_out;           // [L, H]

    float *proj, *xc, *sp, *bcv, *dtv;
    cudaGetSymbolAddress((void**)&proj, g_proj);
    cudaGetSymbolAddress((void**)&xc,   g_xc);
    cudaGetSymbolAddress((void**)&sp,   g_sp);
    cudaGetSymbolAddress((void**)&bcv,  g_bc);
    cudaGetSymbolAddress((void**)&dtv,  g_dt);

    __nv_bfloat16 *hsp, *ipwp, *xcp, *xpwp, *dtrp, *dtpwp, *yp, *opwp;
    cudaGetSymbolAddress((void**)&hsp,   g_hs_p);
    cudaGetSymbolAddress((void**)&ipwp,  g_ipw_p);
    cudaGetSymbolAddress((void**)&xcp,   g_xc_p);
    cudaGetSymbolAddress((void**)&xpwp,  g_xpw_p);
    cudaGetSymbolAddress((void**)&dtrp,  g_dtr_p);
    cudaGetSymbolAddress((void**)&dtpwp, g_dtpw_p);
    cudaGetSymbolAddress((void**)&yp,    g_y_p);
    cudaGetSymbolAddress((void**)&opwp,  g_opw_p);

    cudaFuncSetAttribute(bf16_gemm_abT<0>,
                         cudaFuncAttributeMaxDynamicSharedMemorySize, TG_SMEM_BYTES);
    cudaFuncSetAttribute(bf16_gemm_abT<1>,
                         cudaFuncAttributeMaxDynamicSharedMemorySize, TG_SMEM_BYTES);

    // 0) pre-split static operands into bf16 hi/lo planes
    auto spl = [](const float* s, __nv_bfloat16* p, size_t n) {
        split_kernel<<<(unsigned)((n + 255) / 256), 256>>>(s, p, n);
    };
    spl(hs,         hsp,   (size_t)L_ * H_);
    spl(in_proj_w,  ipwp,  (size_t)2 * I_ * H_);
    spl(x_proj_w,   xpwp,  (size_t)SPN_ * I_);
    spl(dt_proj_w,  dtpwp, (size_t)I_ * R_);
    spl(out_proj_w, opwp,  (size_t)H_ * I_);

    const size_t nHS = (size_t)L_ * H_, nIPW = (size_t)2 * I_ * H_;
    const size_t nXC = (size_t)L_ * I_, nXPW = (size_t)SPN_ * I_;
    const size_t nDTR = (size_t)L_ * R_, nDTPW = (size_t)I_ * R_;
    const size_t nY = (size_t)L_ * I_, nOPW = (size_t)H_ * I_;

    // grid: x = M tiles (col-major wave -> A stays L2-resident), y = N tiles
    // 1) proj[L, 2I] = hs @ in_proj_w^T
    bf16_gemm_abT<0><<<dim3(L_ / 128, 2 * I_ / 128), 256, TG_SMEM_BYTES>>>(
        hsp, hsp + nHS, ipwp, ipwp + nIPW, proj, L_, 2 * I_, H_, H_, nullptr);

    // 2) xc = silu(causal depthwise conv(proj[:, :I]))  (+ bf16 planes)
    conv_silu_kernel<<<(L_ * I_) / 256, 256>>>(proj, conv_w, conv_b, xc, xcp);

    // 3) sp partials = xc @ x_proj_w^T, split-K x4 (z-slices), 128 CTAs
    bf16_gemm_abT<0><<<dim3(L_ / 128, 2, SPLITK_), 256, TG_SMEM_BYTES>>>(
        xcp, xcp + nXC, xpwp, xpwp + nXPW, sp, L_, SPN_, I_ / SPLITK_, I_, nullptr);

    // 4) split-K reduce + per-branch rmsnorm -> dtr planes, bc[L,16x(B,C)]
    rmsnorm_kernel<<<L_ / 4, 128>>>(sp, dt_ln_w, b_ln_w, c_ln_w, dtrp, bcv);

    // 5) dt[L, I] = softplus(dtr @ dt_proj_w^T + dt_proj_b)
    bf16_gemm_abT<1><<<dim3(L_ / 128, I_ / 128), 256, TG_SMEM_BYTES>>>(
        dtrp, dtrp + nDTR, dtpwp, dtpwp + nDTPW, dtv, L_, I_, R_, R_, dt_proj_b);

    // 6) selective scan + (ys + xc*D) * silu(gate) -> y planes
    scan_kernel<<<I_ / 8, 128>>>(xc, dtv, bcv, A, D, proj, yp);

    // 7) out[L, H] = y @ out_proj_w^T
    bf16_gemm_abT<0><<<dim3(L_ / 128, H_ / 128), 256, TG_SMEM_BYTES>>>(
        yp, yp + nY, opwp, opwp + nOPW, out, L_, H_, I_, I_, nullptr);
}